// round 15
// baseline (speedup 1.0000x reference)
#include <cuda_runtime.h>
#include <cuda_fp16.h>
#include <cstdint>
#include <math.h>

// Problem constants
#define BATCH 2
#define DIM   128
#define HH    128
#define WW    128
#define SP    (HH*WW)        // 16384
#define HEADS 4
#define CH    32
#define C3    384
#define PXR   130
#define PXC   132
#define BPER  (2*PXC + 128*4)   // 776 border cells per plane

// ---------------------------------------------------------------------------
// Scratch (__device__ globals)
__device__ __half  g_Wq_hi[4*C3*40];
__device__ __half  g_Wq_lo[4*C3*40];
__device__ __half  g_Wd_hi[108*C3*40];
__device__ __half  g_Wp_hi[4*DIM*40];
__device__ __half  g_Wp_lo[4*DIM*40];
__device__ unsigned short g_Xpd[BATCH*C3*PXR*PXC];   // padded fp16 qkv out
__device__ unsigned short g_y2h[BATCH*C3*SP];        // dw out (q|k|v) fp16
__device__ unsigned short g_aoh[BATCH*DIM*SP];       // attention out fp16 hi
__device__ float g_nq2[BATCH*DIM];
__device__ float g_nk2[BATCH*DIM];
__device__ float g_S[BATCH*HEADS*CH*CH];
__device__ float g_A[BATCH*HEADS*CH*CH];

__constant__ int   c_comp[4][4] = {{0,1,2,3},{1,0,3,2},{2,3,0,1},{3,2,1,0}};
__constant__ float c_sgn [4][4] = {{1.f,-1.f,-1.f,-1.f},
                                   {1.f, 1.f,-1.f, 1.f},
                                   {1.f, 1.f, 1.f,-1.f},
                                   {1.f,-1.f, 1.f, 1.f}};

// ---------------------------------------------------------------------------
__device__ __forceinline__ uint32_t smem_to_u32(const void* p) {
    uint32_t a;
    asm("{ .reg .u64 t; cvta.to.shared.u64 t, %1; cvt.u32.u64 %0, t; }" : "=r"(a) : "l"(p));
    return a;
}
__device__ __forceinline__ void cp16(uint32_t dst, const void* src) {
    asm volatile("cp.async.cg.shared.global [%0], [%1], 16;" :: "r"(dst), "l"(src) : "memory");
}
#define CP_COMMIT() asm volatile("cp.async.commit_group;" ::: "memory")
#define CP_WAIT0()  asm volatile("cp.async.wait_group 0;" ::: "memory")

__device__ __forceinline__ void ldm_x4(uint32_t* r, uint32_t addr) {
    asm volatile("ldmatrix.sync.aligned.m8n8.x4.shared.b16 {%0,%1,%2,%3}, [%4];"
        : "=r"(r[0]), "=r"(r[1]), "=r"(r[2]), "=r"(r[3]) : "r"(addr));
}
__device__ __forceinline__ void ldm_x4_t(uint32_t* r, uint32_t addr) {
    asm volatile("ldmatrix.sync.aligned.m8n8.x4.trans.shared.b16 {%0,%1,%2,%3}, [%4];"
        : "=r"(r[0]), "=r"(r[1]), "=r"(r[2]), "=r"(r[3]) : "r"(addr));
}
__device__ __forceinline__ void mma16816f(float* c, const uint32_t* a, const uint32_t* b) {
    asm volatile("mma.sync.aligned.m16n8k16.row.col.f32.f16.f16.f32 "
        "{%0,%1,%2,%3}, {%4,%5,%6,%7}, {%8,%9}, {%0,%1,%2,%3};"
        : "+f"(c[0]), "+f"(c[1]), "+f"(c[2]), "+f"(c[3])
        : "r"(a[0]), "r"(a[1]), "r"(a[2]), "r"(a[3]), "r"(b[0]), "r"(b[1]));
}

// ---------------------------------------------------------------------------
// Fused prep
__device__ __forceinline__ void expand_one(int idx, const float* r, const float* i,
                                           const float* j, const float* k,
                                           __half* Whi, __half* Wlo, int Bo, int Bi, int K9,
                                           bool writeLo)
{
    int KD = 4*Bi*K9;
    int co = idx / KD;
    int kidx = idx % KD;
    int ci = kidx / K9, r9 = kidx % K9;
    int br = co / Bo, o = co % Bo;
    int bc = ci / Bi, ic = ci % Bi;
    int comp = c_comp[br][bc];
    const float* src = (comp==0) ? r : (comp==1) ? i : (comp==2) ? j : k;
    float v = c_sgn[br][bc] * src[(o*Bi + ic)*K9 + r9];
    __half h = __float2half(v);
    int chunk = kidx >> 5, kk = kidx & 31;
    size_t dst = ((size_t)chunk*(4*Bo) + co)*40 + kk;
    Whi[dst] = h;
    if (writeLo) Wlo[dst] = __float2half(v - __half2float(h));
}

#define N1 (16*96*96*9)
#define N2 (16*96*32)
#define N3 (16*32*32)
#define N4 (BATCH*C3*BPER)
#define N5 (8192 + 512)
#define NTOT (N1+N2+N3+N4+N5)

__global__ void prep_kernel(const float* __restrict__ qr, const float* __restrict__ qi,
                            const float* __restrict__ qj, const float* __restrict__ qk,
                            const float* __restrict__ dr, const float* __restrict__ di,
                            const float* __restrict__ dj, const float* __restrict__ dk,
                            const float* __restrict__ pr, const float* __restrict__ pi,
                            const float* __restrict__ pj, const float* __restrict__ pk,
                            __half* __restrict__ Wq_hi, __half* __restrict__ Wq_lo,
                            __half* __restrict__ Wd_hi,
                            __half* __restrict__ Wp_hi, __half* __restrict__ Wp_lo,
                            unsigned short* __restrict__ Xpd, float* __restrict__ Sm,
                            float* __restrict__ nq2, float* __restrict__ nk2)
{
    int idx = blockIdx.x*blockDim.x + threadIdx.x;
    if (idx < N1) {
        expand_one(idx, dr, di, dj, dk, Wd_hi, nullptr, 96, 96, 9, false);
    } else if (idx < N1+N2) {
        expand_one(idx - N1, qr, qi, qj, qk, Wq_hi, Wq_lo, 96, 32, 1, true);
    } else if (idx < N1+N2+N3) {
        expand_one(idx - N1 - N2, pr, pi, pj, pk, Wp_hi, Wp_lo, 32, 32, 1, true);
    } else if (idx < N1+N2+N3+N4) {
        int t = idx - N1 - N2 - N3;
        int plane = t / BPER, r = t % BPER;
        unsigned short* p = Xpd + (size_t)plane*PXR*PXC;
        int row, col;
        if (r < 2*PXC) { row = (r < PXC) ? 0 : (PXR-1); col = r % PXC; }
        else { int u = r - 2*PXC; row = 1 + (u >> 2); int c4 = u & 3; col = (c4==0) ? 0 : (128 + c4); }
        p[row*PXC + col] = 0;
    } else if (idx < NTOT) {
        int t = idx - N1 - N2 - N3 - N4;
        if (t < 8192) Sm[t] = 0.f;
        else if (t < 8448) nq2[t-8192] = 0.f;
        else nk2[t-8448] = 0.f;
    }
}

// ---------------------------------------------------------------------------
// Unified implicit-GEMM conv on mma.sync (fp16, fp32 accum)
// KSZ==3: B staged via row-scratch (each (ci,ky) row loaded ONCE, expanded to
//         3 kx-shifted B rows from smem) — kills im2col sector waste.
// KSZ==1: direct register-prefetch gather (INTY 0=float, 1=ushort).
template<int CIN, int KSZ, int COUT, bool ALO, int INTY, int OUTMODE>
__global__ __launch_bounds__(256)
void convmma_kernel(const __half* __restrict__ Whi, const __half* __restrict__ Wlo,
                    const void* __restrict__ Xin, const float* __restrict__ bias,
                    float* __restrict__ Yf, unsigned short* __restrict__ Yh,
                    int PR, int PC)
{
    constexpr int K    = CIN*KSZ*KSZ;
    constexpr int KCn  = K/32;
    constexpr int S_AL = 10240;
    constexpr int S_BH = ALO ? 20480 : 10240;
    constexpr int S_SC = S_BH + 8704;                   // scratch (KSZ==3)
    constexpr int S_SZ = (KSZ==3) ? (S_SC + 3200) : (S_BH + 8704);

    extern __shared__ char smc[];
    const uint32_t sb = smem_to_u32(smc);
    const int tid = threadIdx.x, lane = tid & 31, wid = tid >> 5;
    const int bx = blockIdx.x;
    const int b  = bx >> 7;
    const int y  = bx & 127;
    const int co0 = blockIdx.y * 128;
    const int warp_m = wid >> 2;
    const int warp_n = wid & 3;

    float acc[4][4][4];
#pragma unroll
    for (int a = 0; a < 4; a++)
#pragma unroll
        for (int c = 0; c < 4; c++)
#pragma unroll
            for (int e = 0; e < 4; e++) acc[a][c][e] = 0.f;

    const int kb  = tid >> 3;
    const int pxb = tid & 7;

    // ---- prologue: stage chunk 0 ----
    {
        const char* sh = (const char*)(Whi + (size_t)co0*40);
        for (int t2 = tid; t2 < 640; t2 += 256) cp16(sb + t2*16, sh + t2*16);
        if (ALO) {
            const char* sl = (const char*)(Wlo + (size_t)co0*40);
            for (int t2 = tid; t2 < 640; t2 += 256) cp16(sb + S_AL + t2*16, sl + t2*16);
        }
        CP_COMMIT();
        if constexpr (KSZ == 3) {
            // scratch fill chunk 0 (rows j = 0..11)
            const uint32_t* X32 = (const uint32_t*)Xin;
            for (int t2 = tid; t2 < 792; t2 += 256) {
                int jr = t2/66, cg = t2 - jr*66;
                int j = jr; if (j > CIN*3-1) j = CIN*3-1;
                int ci = j/3, ky = j - ci*3;
                size_t rb = ((size_t)(b*CIN + ci)*PR + (y + ky))*PC >> 1;
                *(uint32_t*)(smc + S_SC + t2*4) = X32[rb + cg];
            }
            __syncthreads();
            // expand scratch -> B tile
            {
                int kg = kb;
                int j = kg/3, kx = kg - j*3;
                const unsigned short* srow = (const unsigned short*)(smc + S_SC) + j*132 + kx;
                int ro = kb*136 + pxb;
#pragma unroll
                for (int i2 = 0; i2 < 16; i2++)
                    *(unsigned short*)(smc + S_BH + (ro + 8*i2)*2) = srow[pxb + 8*i2];
            }
        } else {
            size_t base = ((size_t)(b*CIN + kb)*PR + y)*PC + pxb;
            int ro = kb*136 + pxb;
            if constexpr (INTY == 0) {
                const float* src = (const float*)Xin + base;
#pragma unroll
                for (int i2 = 0; i2 < 16; i2++)
                    *(unsigned short*)(smc + S_BH + (ro + 8*i2)*2) =
                        __half_as_ushort(__float2half(src[8*i2]));
            } else {
                const unsigned short* src = (const unsigned short*)Xin + base;
#pragma unroll
                for (int i2 = 0; i2 < 16; i2++)
                    *(unsigned short*)(smc + S_BH + (ro + 8*i2)*2) = src[8*i2];
            }
        }
        CP_WAIT0();
        __syncthreads();
    }

    const int quad = lane >> 3, qi = lane & 7;

    for (int it = 0; it < KCn; it++) {
        const int s = it & 1;
        const uint32_t stage  = sb + s*S_SZ;
        const uint32_t nstoff = (s^1)*S_SZ;
        const bool hasNext = (it + 1) < KCn;

        float gf[16];
        unsigned short gs[16];
        if (hasNext) {
            const char* sh = (const char*)(Whi + ((size_t)(it+1)*COUT + co0)*40);
            for (int t2 = tid; t2 < 640; t2 += 256) cp16(sb + nstoff + t2*16, sh + t2*16);
            if (ALO) {
                const char* sl = (const char*)(Wlo + ((size_t)(it+1)*COUT + co0)*40);
                for (int t2 = tid; t2 < 640; t2 += 256) cp16(sb + nstoff + S_AL + t2*16, sl + t2*16);
            }
            CP_COMMIT();
            if constexpr (KSZ == 3) {
                // coalesced scratch fill for next chunk
                int jb = ((it+1)*32)/3;
                const uint32_t* X32 = (const uint32_t*)Xin;
                for (int t2 = tid; t2 < 792; t2 += 256) {
                    int jr = t2/66, cg = t2 - jr*66;
                    int j = jb + jr; if (j > CIN*3-1) j = CIN*3-1;
                    int ci = j/3, ky = j - ci*3;
                    size_t rb = ((size_t)(b*CIN + ci)*PR + (y + ky))*PC >> 1;
                    *(uint32_t*)(smc + nstoff + S_SC + t2*4) = X32[rb + cg];
                }
            } else {
                size_t base = ((size_t)(b*CIN + (it+1)*32 + kb)*PR + y)*PC + pxb;
                if constexpr (INTY == 0) {
                    const float* src = (const float*)Xin + base;
#pragma unroll
                    for (int i2 = 0; i2 < 16; i2++) gf[i2] = src[8*i2];
                } else {
                    const unsigned short* src = (const unsigned short*)Xin + base;
#pragma unroll
                    for (int i2 = 0; i2 < 16; i2++) gs[i2] = src[8*i2];
                }
            }
        }

        // ---- mma on current stage ----
#pragma unroll
        for (int ks = 0; ks < 2; ks++) {
            const int k0 = ks*16;
            uint32_t Ah[4][4], Al[4][4], Bh[4][2];
            const int arow = warp_m*64 + (quad&1)*8 + qi;
            const int acol = k0 + (quad>>1)*8;
#pragma unroll
            for (int mf = 0; mf < 4; mf++) {
                uint32_t ad = stage + (uint32_t)((arow + mf*16)*40 + acol)*2;
                ldm_x4(Ah[mf], ad);
                if (ALO) ldm_x4(Al[mf], ad + S_AL);
            }
            const int brow = k0 + (quad&1)*8 + qi;
#pragma unroll
            for (int p2 = 0; p2 < 2; p2++) {
                const int n0 = warp_n*32 + p2*16 + (quad>>1)*8;
                uint32_t bd = stage + S_BH + (uint32_t)(brow*136 + n0)*2;
                uint32_t r4[4];
                ldm_x4_t(r4, bd);
                Bh[p2*2][0]=r4[0]; Bh[p2*2][1]=r4[1]; Bh[p2*2+1][0]=r4[2]; Bh[p2*2+1][1]=r4[3];
            }
#pragma unroll
            for (int mf = 0; mf < 4; mf++)
#pragma unroll
                for (int nf = 0; nf < 4; nf++) {
                    mma16816f(acc[mf][nf], Ah[mf], Bh[nf]);
                    if (ALO) mma16816f(acc[mf][nf], Al[mf], Bh[nf]);
                }
        }

        if constexpr (KSZ == 3) {
            __syncthreads();    // scratch(next) complete + MMA done
            if (hasNext) {
                int cit = it + 1, jb = (cit*32)/3;
                int kg = cit*32 + kb;
                int jj = kg/3;
                int j = jj - jb, kx = kg - jj*3;
                const unsigned short* srow = (const unsigned short*)(smc + nstoff + S_SC) + j*132 + kx;
                int ro = kb*136 + pxb;
#pragma unroll
                for (int i2 = 0; i2 < 16; i2++)
                    *(unsigned short*)(smc + nstoff + S_BH + (ro + 8*i2)*2) = srow[pxb + 8*i2];
            }
        } else if (hasNext) {
            int ro = kb*136 + pxb;
            if constexpr (INTY == 0) {
#pragma unroll
                for (int i2 = 0; i2 < 16; i2++)
                    *(unsigned short*)(smc + nstoff + S_BH + (ro + 8*i2)*2) =
                        __half_as_ushort(__float2half(gf[i2]));
            } else {
#pragma unroll
                for (int i2 = 0; i2 < 16; i2++)
                    *(unsigned short*)(smc + nstoff + S_BH + (ro + 8*i2)*2) = gs[i2];
            }
        }
        CP_WAIT0();
        __syncthreads();
    }

    // ---- epilogue ----
    const int r = lane >> 2, cpx = (lane & 3)*2;
#pragma unroll
    for (int mf = 0; mf < 4; mf++) {
        int coA = co0 + warp_m*64 + mf*16 + r;
        float b0 = bias[coA], b1 = bias[coA + 8];
#pragma unroll
        for (int nf = 0; nf < 4; nf++) {
            int px = warp_n*32 + nf*8 + cpx;
            float v00 = acc[mf][nf][0] + b0, v01 = acc[mf][nf][1] + b0;
            float v10 = acc[mf][nf][2] + b1, v11 = acc[mf][nf][3] + b1;
            if constexpr (OUTMODE == 1) {
                size_t r0 = ((size_t)(b*COUT + coA    )*PXR + (y+1))*PXC + (px+1);
                size_t r1 = ((size_t)(b*COUT + coA + 8)*PXR + (y+1))*PXC + (px+1);
                Yh[r0]   = __half_as_ushort(__float2half(v00));
                Yh[r0+1] = __half_as_ushort(__float2half(v01));
                Yh[r1]   = __half_as_ushort(__float2half(v10));
                Yh[r1+1] = __half_as_ushort(__float2half(v11));
            } else if constexpr (OUTMODE == 2) {
                uint32_t p0 = (uint32_t)__half_as_ushort(__float2half(v00)) |
                              ((uint32_t)__half_as_ushort(__float2half(v01)) << 16);
                uint32_t p1 = (uint32_t)__half_as_ushort(__float2half(v10)) |
                              ((uint32_t)__half_as_ushort(__float2half(v11)) << 16);
                *(uint32_t*)&Yh[((size_t)(b*COUT + coA    ))*SP + y*WW + px] = p0;
                *(uint32_t*)&Yh[((size_t)(b*COUT + coA + 8))*SP + y*WW + px] = p1;
            } else {
                float2 w0 = {v00, v01}, w1 = {v10, v11};
                *(float2*)&Yf[((size_t)(b*COUT + coA    ))*SP + y*WW + px] = w0;
                *(float2*)&Yf[((size_t)(b*COUT + coA + 8))*SP + y*WW + px] = w1;
            }
        }
    }
}

// ---------------------------------------------------------------------------
// QK Gram matrix + fused row norms. grid (8 bh, 16 slices), 256 threads
__global__ __launch_bounds__(256)
void qk_mma_kernel(const unsigned short* __restrict__ y2h, float* __restrict__ Sm,
                   float* __restrict__ nq2, float* __restrict__ nk2)
{
    __shared__ __half qs[32][136];
    __shared__ __half ksT[128][40];
    __shared__ float  Ssm[32][32];
    __shared__ float  qrow[32], krow[32];

    const int bh = blockIdx.x;
    const int b  = bh >> 2, h = bh & 3;
    const int s0 = blockIdx.y * 1024;
    const int tid = threadIdx.x, lane = tid & 31, w = tid >> 5;
    const int quad = lane >> 3, qi = lane & 7;

    const unsigned short* q = y2h + (size_t)b*C3*SP + (size_t)(h*CH)*SP;
    const unsigned short* k = q + (size_t)DIM*SP;

    for (int l = tid; l < 1024; l += 256) Ssm[l >> 5][l & 31] = 0.f;
    if (tid < 32) { qrow[tid] = 0.f; krow[tid] = 0.f; }

    const uint32_t sq = smem_to_u32(&qs[0][0]);
    const uint32_t sk = smem_to_u32(&ksT[0][0]);

    float acc[2][4][4];
#pragma unroll
    for (int mf = 0; mf < 2; mf++)
#pragma unroll
        for (int nf = 0; nf < 4; nf++)
#pragma unroll
            for (int e = 0; e < 4; e++) acc[mf][nf][e] = 0.f;

    // fixed rows for this thread's two q-staging slots
    const int qrow0 = tid >> 4;             // slot tid
    const int qcg0  = tid & 15;
    float sq0 = 0.f, sq1 = 0.f, ksum = 0.f;
    const int kd    = tid >> 3;             // k staging row
    const int ksb   = (tid & 7)*16;

    for (int rnd = 0; rnd < 8; rnd++) {
        const int ss = s0 + rnd*128;
        // q staging: slots tid and tid+256 (rows qrow0 and qrow0+16)
        {
            uint4 v0 = *(const uint4*)&q[(size_t)qrow0*SP + ss + qcg0*8];
            uint4 v1 = *(const uint4*)&q[(size_t)(qrow0+16)*SP + ss + qcg0*8];
            *(uint4*)&qs[qrow0][qcg0*8]    = v0;
            *(uint4*)&qs[qrow0+16][qcg0*8] = v1;
            const __half2* h0 = (const __half2*)&v0;
            const __half2* h1 = (const __half2*)&v1;
#pragma unroll
            for (int e = 0; e < 4; e++) {
                float a0 = __low2float(h0[e]), b0 = __high2float(h0[e]);
                float a1 = __low2float(h1[e]), b1 = __high2float(h1[e]);
                sq0 += a0*a0 + b0*b0;
                sq1 += a1*a1 + b1*b1;
            }
        }
        // k staging (transposed) + norm accum
        {
            const unsigned short* kp = &k[(size_t)kd*SP + ss + ksb];
            unsigned short tmp[16];
#pragma unroll
            for (int i2 = 0; i2 < 16; i2++) tmp[i2] = kp[i2];
#pragma unroll
            for (int i2 = 0; i2 < 16; i2++) {
                __half hv = __ushort_as_half(tmp[i2]);
                ksT[ksb + i2][kd] = hv;
                float f = __half2float(hv);
                ksum += f*f;
            }
        }
        __syncthreads();

        uint32_t Af[2][4], Bf[4][2];
#pragma unroll
        for (int mf = 0; mf < 2; mf++) {
            uint32_t ad = sq + (uint32_t)((mf*16 + (quad&1)*8 + qi)*136 + w*16 + (quad>>1)*8)*2;
            ldm_x4(Af[mf], ad);
        }
#pragma unroll
        for (int p2 = 0; p2 < 2; p2++) {
            uint32_t bd = sk + (uint32_t)((w*16 + (quad&1)*8 + qi)*40 + p2*16 + (quad>>1)*8)*2;
            uint32_t r4[4];
            ldm_x4_t(r4, bd);
            Bf[p2*2][0]=r4[0]; Bf[p2*2][1]=r4[1]; Bf[p2*2+1][0]=r4[2]; Bf[p2*2+1][1]=r4[3];
        }
#pragma unroll
        for (int mf = 0; mf < 2; mf++)
#pragma unroll
            for (int nf = 0; nf < 4; nf++)
                mma16816f(acc[mf][nf], Af[mf], Bf[nf]);
        __syncthreads();
    }

    // reduce norms
    atomicAdd(&qrow[qrow0], sq0);
    atomicAdd(&qrow[qrow0+16], sq1);
    atomicAdd(&krow[kd], ksum);

    // reduce partial S into shared, then global
    const int r = lane >> 2, cpx = (lane & 3)*2;
#pragma unroll
    for (int mf = 0; mf < 2; mf++)
#pragma unroll
        for (int nf = 0; nf < 4; nf++) {
            atomicAdd(&Ssm[mf*16 + r    ][nf*8 + cpx    ], acc[mf][nf][0]);
            atomicAdd(&Ssm[mf*16 + r    ][nf*8 + cpx + 1], acc[mf][nf][1]);
            atomicAdd(&Ssm[mf*16 + r + 8][nf*8 + cpx    ], acc[mf][nf][2]);
            atomicAdd(&Ssm[mf*16 + r + 8][nf*8 + cpx + 1], acc[mf][nf][3]);
        }
    __syncthreads();
    for (int l = tid; l < 1024; l += 256)
        atomicAdd(&Sm[bh*1024 + l], Ssm[l >> 5][l & 31]);
    if (tid < 32) {
        atomicAdd(&nq2[b*DIM + h*CH + tid], qrow[tid]);
        atomicAdd(&nk2[b*DIM + h*CH + tid], krow[tid]);
    }
}

__global__ __launch_bounds__(1024)
void softmax_kernel(const float* __restrict__ Sm, const float* __restrict__ nq2,
                    const float* __restrict__ nk2, const float* __restrict__ temp,
                    float* __restrict__ Am)
{
    const int bh = blockIdx.x;
    const int b  = bh >> 2, h = bh & 3;
    const int c  = threadIdx.x >> 5;
    const int d  = threadIdx.x & 31;

    float qn = fmaxf(sqrtf(nq2[b*DIM + h*CH + c]), 1e-12f);
    float kn = fmaxf(sqrtf(nk2[b*DIM + h*CH + d]), 1e-12f);
    float v  = Sm[bh*1024 + c*32 + d] / (qn * kn) * temp[h];

    float m = v;
#pragma unroll
    for (int o = 16; o; o >>= 1) m = fmaxf(m, __shfl_xor_sync(~0u, m, o));
    float e = __expf(v - m);
    float s = e;
#pragma unroll
    for (int o = 16; o; o >>= 1) s += __shfl_xor_sync(~0u, s, o);
    Am[bh*1024 + c*32 + d] = e / s;
}

// ---------------------------------------------------------------------------
// AV on mma.sync (unchanged)
__global__ __launch_bounds__(256)
void av_mma_kernel(const unsigned short* __restrict__ y2h, const float* __restrict__ Am,
                   unsigned short* __restrict__ aoh)
{
    __shared__ __half As[32][40];
    __shared__ __half Vs[32][136];

    const int bh = blockIdx.x;
    const int b  = bh >> 2, h = bh & 3;
    const int s0 = blockIdx.y * 1024;
    const int tid = threadIdx.x, lane = tid & 31, w = tid >> 5;
    const int quad = lane >> 3, qi = lane & 7;

    const unsigned short* v = y2h + (size_t)b*C3*SP + (size_t)(2*DIM + h*CH)*SP;
    unsigned short* o = aoh + (size_t)b*DIM*SP + (size_t)(h*CH)*SP;

    for (int l = tid; l < 1024; l += 256)
        As[l >> 5][l & 31] = __float2half(Am[bh*1024 + l]);

    const uint32_t sa = smem_to_u32(&As[0][0]);
    const uint32_t sv = smem_to_u32(&Vs[0][0]);
    const int r = lane >> 2, cpx = (lane & 3)*2;

    for (int rnd = 0; rnd < 8; rnd++) {
        const int ss = s0 + rnd*128;
        for (int t2 = tid; t2 < 512; t2 += 256) {
            int row = t2 >> 4, cg = t2 & 15;
            *(uint4*)&Vs[row][cg*8] = *(const uint4*)&v[(size_t)row*SP + ss + cg*8];
        }
        __syncthreads();

        float acc[2][2][4];
#pragma unroll
        for (int mf = 0; mf < 2; mf++)
#pragma unroll
            for (int nf = 0; nf < 2; nf++)
#pragma unroll
                for (int e = 0; e < 4; e++) acc[mf][nf][e] = 0.f;

#pragma unroll
        for (int ks = 0; ks < 2; ks++) {
            const int k0 = ks*16;
            uint32_t Af[2][4], Bf[2][2];
#pragma unroll
            for (int mf = 0; mf < 2; mf++) {
                uint32_t ad = sa + (uint32_t)((mf*16 + (quad&1)*8 + qi)*40 + k0 + (quad>>1)*8)*2;
                ldm_x4(Af[mf], ad);
            }
            {
                uint32_t bd = sv + (uint32_t)((k0 + (quad&1)*8 + qi)*136 + w*16 + (quad>>1)*8)*2;
                uint32_t r4[4];
                ldm_x4_t(r4, bd);
                Bf[0][0]=r4[0]; Bf[0][1]=r4[1]; Bf[1][0]=r4[2]; Bf[1][1]=r4[3];
            }
#pragma unroll
            for (int mf = 0; mf < 2; mf++)
#pragma unroll
                for (int nf = 0; nf < 2; nf++)
                    mma16816f(acc[mf][nf], Af[mf], Bf[nf]);
        }

#pragma unroll
        for (int mf = 0; mf < 2; mf++)
#pragma unroll
            for (int nf = 0; nf < 2; nf++) {
                int c0 = mf*16 + r;
                int sx = ss + w*16 + nf*8 + cpx;
                uint32_t p0 = (uint32_t)__half_as_ushort(__float2half(acc[mf][nf][0])) |
                              ((uint32_t)__half_as_ushort(__float2half(acc[mf][nf][1])) << 16);
                uint32_t p1 = (uint32_t)__half_as_ushort(__float2half(acc[mf][nf][2])) |
                              ((uint32_t)__half_as_ushort(__float2half(acc[mf][nf][3])) << 16);
                *(uint32_t*)&o[(size_t)(c0    )*SP + sx] = p0;
                *(uint32_t*)&o[(size_t)(c0 + 8)*SP + sx] = p1;
            }
        __syncthreads();
    }
}

// ---------------------------------------------------------------------------
extern "C" void kernel_launch(void* const* d_in, const int* in_sizes, int n_in,
                              void* d_out, int out_size)
{
    const float* x      = (const float*)d_in[0];
    const float* qkv_r  = (const float*)d_in[1];
    const float* qkv_i  = (const float*)d_in[2];
    const float* qkv_j  = (const float*)d_in[3];
    const float* qkv_k  = (const float*)d_in[4];
    const float* qkv_b  = (const float*)d_in[5];
    const float* dw_r   = (const float*)d_in[6];
    const float* dw_i   = (const float*)d_in[7];
    const float* dw_j   = (const float*)d_in[8];
    const float* dw_k   = (const float*)d_in[9];
    const float* dw_b   = (const float*)d_in[10];
    const float* po_r   = (const float*)d_in[11];
    const float* po_i   = (const float*)d_in[12];
    const float* po_j   = (const float*)d_in[13];
    const float* po_k   = (const float*)d_in[14];
    const float* po_b   = (const float*)d_in[15];
    const float* temper = (const float*)d_in[16];
    float* out = (float*)d_out;

    __half *Wq_hi, *Wq_lo, *Wd_hi, *Wp_hi, *Wp_lo;
    unsigned short *Xpd, *y2h, *aoh;
    float *nq2, *nk2, *Sm, *Am;
    cudaGetSymbolAddress((void**)&Wq_hi, g_Wq_hi);
    cudaGetSymbolAddress((void**)&Wq_lo, g_Wq_lo);
    cudaGetSymbolAddress((void**)&Wd_hi, g_Wd_hi);
    cudaGetSymbolAddress((void**)&Wp_hi, g_Wp_hi);
    cudaGetSymbolAddress((void**)&Wp_lo, g_Wp_lo);
    cudaGetSymbolAddress((void**)&Xpd, g_Xpd);
    cudaGetSymbolAddress((void**)&y2h, g_y2h);
    cudaGetSymbolAddress((void**)&aoh, g_aoh);
    cudaGetSymbolAddress((void**)&nq2, g_nq2);
    cudaGetSymbolAddress((void**)&nk2, g_nk2);
    cudaGetSymbolAddress((void**)&Sm, g_S);
    cudaGetSymbolAddress((void**)&Am, g_A);

    const int SMQ = 58368;   // 2-pass A-split stages (KSZ=1)
    const int SM1 = 44288;   // dw: 1-pass + scratch
    cudaFuncSetAttribute(convmma_kernel<128,1,384,true,0,1>,
                         cudaFuncAttributeMaxDynamicSharedMemorySize, SMQ);
    cudaFuncSetAttribute(convmma_kernel<384,3,384,false,1,2>,
                         cudaFuncAttributeMaxDynamicSharedMemorySize, SM1);
    cudaFuncSetAttribute(convmma_kernel<128,1,128,true,1,0>,
                         cudaFuncAttributeMaxDynamicSharedMemorySize, SMQ);

    // 1) fused prep
    prep_kernel<<<(NTOT + 255)/256, 256>>>(
        qkv_r, qkv_i, qkv_j, qkv_k, dw_r, dw_i, dw_j, dw_k, po_r, po_i, po_j, po_k,
        Wq_hi, Wq_lo, Wd_hi, Wp_hi, Wp_lo, Xpd, Sm, nq2, nk2);

    // 2) qkv 1x1 conv
    convmma_kernel<128,1,384,true,0,1><<<dim3(BATCH*HH, 3), 256, SMQ>>>(
        Wq_hi, Wq_lo, x, qkv_b, nullptr, Xpd, HH, WW);

    // 3) dw 3x3 conv (scratch-expanded B staging)
    convmma_kernel<384,3,384,false,1,2><<<dim3(BATCH*HH, 3), 256, SM1>>>(
        Wd_hi, Wd_hi, Xpd, dw_b, nullptr, y2h, PXR, PXC);

    // 4) attention (norms fused into qk)
    qk_mma_kernel<<<dim3(8, 16), 256>>>(y2h, Sm, nq2, nk2);
    softmax_kernel<<<8, 1024>>>(Sm, nq2, nk2, temper, Am);
    av_mma_kernel<<<dim3(8, 16), 256>>>(y2h, Am, aoh);

    // 5) po 1x1 conv -> out
    convmma_kernel<128,1,128,true,1,0><<<dim3(BATCH*HH, 1), 256, SMQ>>>(
        Wp_hi, Wp_lo, aoh, po_b, out, nullptr, HH, WW);
}

// round 16
// speedup vs baseline: 1.4617x; 1.4617x over previous
#include <cuda_runtime.h>
#include <cuda_fp16.h>
#include <cstdint>
#include <math.h>

// Problem constants
#define BATCH 2
#define DIM   128
#define HH    128
#define WW    128
#define SP    (HH*WW)        // 16384
#define HEADS 4
#define CH    32
#define C3    384
#define PXR   130
#define PXC   132
#define BPER  (2*PXC + 128*4)   // 776 border cells per plane

// ---------------------------------------------------------------------------
// Scratch (__device__ globals)
__device__ __half  g_Wq_hi[4*C3*40];
__device__ __half  g_Wq_lo[4*C3*40];
__device__ __half  g_Wd_hi[108*C3*40];
__device__ __half  g_Wp_hi[4*DIM*40];
__device__ __half  g_Wp_lo[4*DIM*40];
__device__ unsigned short g_Xpd[BATCH*C3*PXR*PXC];   // padded fp16 qkv out
__device__ unsigned short g_y2h[BATCH*C3*SP];        // dw out (q|k|v) fp16
__device__ unsigned short g_aoh[BATCH*DIM*SP];       // attention out fp16 hi
__device__ float g_nq2[BATCH*DIM];
__device__ float g_nk2[BATCH*DIM];
__device__ float g_S[BATCH*HEADS*CH*CH];
__device__ float g_A[BATCH*HEADS*CH*CH];

__constant__ int   c_comp[4][4] = {{0,1,2,3},{1,0,3,2},{2,3,0,1},{3,2,1,0}};
__constant__ float c_sgn [4][4] = {{1.f,-1.f,-1.f,-1.f},
                                   {1.f, 1.f,-1.f, 1.f},
                                   {1.f, 1.f, 1.f,-1.f},
                                   {1.f,-1.f, 1.f, 1.f}};

// ---------------------------------------------------------------------------
__device__ __forceinline__ uint32_t smem_to_u32(const void* p) {
    uint32_t a;
    asm("{ .reg .u64 t; cvta.to.shared.u64 t, %1; cvt.u32.u64 %0, t; }" : "=r"(a) : "l"(p));
    return a;
}
__device__ __forceinline__ void cp16(uint32_t dst, const void* src) {
    asm volatile("cp.async.cg.shared.global [%0], [%1], 16;" :: "r"(dst), "l"(src) : "memory");
}
#define CP_COMMIT() asm volatile("cp.async.commit_group;" ::: "memory")
#define CP_WAIT0()  asm volatile("cp.async.wait_group 0;" ::: "memory")

__device__ __forceinline__ void ldm_x4(uint32_t* r, uint32_t addr) {
    asm volatile("ldmatrix.sync.aligned.m8n8.x4.shared.b16 {%0,%1,%2,%3}, [%4];"
        : "=r"(r[0]), "=r"(r[1]), "=r"(r[2]), "=r"(r[3]) : "r"(addr));
}
__device__ __forceinline__ void ldm_x4_t(uint32_t* r, uint32_t addr) {
    asm volatile("ldmatrix.sync.aligned.m8n8.x4.trans.shared.b16 {%0,%1,%2,%3}, [%4];"
        : "=r"(r[0]), "=r"(r[1]), "=r"(r[2]), "=r"(r[3]) : "r"(addr));
}
__device__ __forceinline__ void mma16816f(float* c, const uint32_t* a, const uint32_t* b) {
    asm volatile("mma.sync.aligned.m16n8k16.row.col.f32.f16.f16.f32 "
        "{%0,%1,%2,%3}, {%4,%5,%6,%7}, {%8,%9}, {%0,%1,%2,%3};"
        : "+f"(c[0]), "+f"(c[1]), "+f"(c[2]), "+f"(c[3])
        : "r"(a[0]), "r"(a[1]), "r"(a[2]), "r"(a[3]), "r"(b[0]), "r"(b[1]));
}

// ---------------------------------------------------------------------------
// Fused prep (zeroes Sm + nq2 + nk2, expands all weights, zeroes pad borders)
__device__ __forceinline__ void expand_one(int idx, const float* r, const float* i,
                                           const float* j, const float* k,
                                           __half* Whi, __half* Wlo, int Bo, int Bi, int K9,
                                           bool writeLo)
{
    int KD = 4*Bi*K9;
    int co = idx / KD;
    int kidx = idx % KD;
    int ci = kidx / K9, r9 = kidx % K9;
    int br = co / Bo, o = co % Bo;
    int bc = ci / Bi, ic = ci % Bi;
    int comp = c_comp[br][bc];
    const float* src = (comp==0) ? r : (comp==1) ? i : (comp==2) ? j : k;
    float v = c_sgn[br][bc] * src[(o*Bi + ic)*K9 + r9];
    __half h = __float2half(v);
    int chunk = kidx >> 5, kk = kidx & 31;
    size_t dst = ((size_t)chunk*(4*Bo) + co)*40 + kk;
    Whi[dst] = h;
    if (writeLo) Wlo[dst] = __float2half(v - __half2float(h));
}

#define N1 (16*96*96*9)
#define N2 (16*96*32)
#define N3 (16*32*32)
#define N4 (BATCH*C3*BPER)
#define N5 (8192 + 512)
#define NTOT (N1+N2+N3+N4+N5)

__global__ void prep_kernel(const float* __restrict__ qr, const float* __restrict__ qi,
                            const float* __restrict__ qj, const float* __restrict__ qk,
                            const float* __restrict__ dr, const float* __restrict__ di,
                            const float* __restrict__ dj, const float* __restrict__ dk,
                            const float* __restrict__ pr, const float* __restrict__ pi,
                            const float* __restrict__ pj, const float* __restrict__ pk,
                            __half* __restrict__ Wq_hi, __half* __restrict__ Wq_lo,
                            __half* __restrict__ Wd_hi,
                            __half* __restrict__ Wp_hi, __half* __restrict__ Wp_lo,
                            unsigned short* __restrict__ Xpd, float* __restrict__ Sm,
                            float* __restrict__ nq2, float* __restrict__ nk2)
{
    int idx = blockIdx.x*blockDim.x + threadIdx.x;
    if (idx < N1) {
        expand_one(idx, dr, di, dj, dk, Wd_hi, nullptr, 96, 96, 9, false);
    } else if (idx < N1+N2) {
        expand_one(idx - N1, qr, qi, qj, qk, Wq_hi, Wq_lo, 96, 32, 1, true);
    } else if (idx < N1+N2+N3) {
        expand_one(idx - N1 - N2, pr, pi, pj, pk, Wp_hi, Wp_lo, 32, 32, 1, true);
    } else if (idx < N1+N2+N3+N4) {
        int t = idx - N1 - N2 - N3;
        int plane = t / BPER, r = t % BPER;
        unsigned short* p = Xpd + (size_t)plane*PXR*PXC;
        int row, col;
        if (r < 2*PXC) { row = (r < PXC) ? 0 : (PXR-1); col = r % PXC; }
        else { int u = r - 2*PXC; row = 1 + (u >> 2); int c4 = u & 3; col = (c4==0) ? 0 : (128 + c4); }
        p[row*PXC + col] = 0;
    } else if (idx < NTOT) {
        int t = idx - N1 - N2 - N3 - N4;
        if (t < 8192) Sm[t] = 0.f;
        else if (t < 8448) nq2[t-8192] = 0.f;
        else nk2[t-8448] = 0.f;
    }
}

// ---------------------------------------------------------------------------
// Unified implicit-GEMM conv on mma.sync (round-13 proven version:
// direct register-prefetch im2col gather, double-buffered smem pipeline)
template<int CIN, int KSZ, int COUT, bool ALO, int INTY, int OUTMODE>
__global__ __launch_bounds__(256)
void convmma_kernel(const __half* __restrict__ Whi, const __half* __restrict__ Wlo,
                    const void* __restrict__ Xin, const float* __restrict__ bias,
                    float* __restrict__ Yf, unsigned short* __restrict__ Yh,
                    int PR, int PC)
{
    constexpr int K    = CIN*KSZ*KSZ;
    constexpr int KCn  = K/32;
    constexpr int S_AL = 10240;
    constexpr int S_BH = ALO ? 20480 : 10240;
    constexpr int S_SZ = S_BH + 8704;

    extern __shared__ char smc[];
    const uint32_t sb = smem_to_u32(smc);
    const int tid = threadIdx.x, lane = tid & 31, wid = tid >> 5;
    const int bx = blockIdx.x;
    const int b  = bx >> 7;
    const int y  = bx & 127;
    const int co0 = blockIdx.y * 128;
    const int warp_m = wid >> 2;
    const int warp_n = wid & 3;

    float acc[4][4][4];
#pragma unroll
    for (int a = 0; a < 4; a++)
#pragma unroll
        for (int c = 0; c < 4; c++)
#pragma unroll
            for (int e = 0; e < 4; e++) acc[a][c][e] = 0.f;

    const int kb  = tid >> 3;
    const int pxb = tid & 7;

    {
        const char* sh = (const char*)(Whi + (size_t)co0*40);
        for (int t2 = tid; t2 < 640; t2 += 256) cp16(sb + t2*16, sh + t2*16);
        if (ALO) {
            const char* sl = (const char*)(Wlo + (size_t)co0*40);
            for (int t2 = tid; t2 < 640; t2 += 256) cp16(sb + S_AL + t2*16, sl + t2*16);
        }
        CP_COMMIT();
        int kg = kb;
        int ci, ky, kx;
        if (KSZ == 3) { ci = kg/9; int r9 = kg - ci*9; ky = r9/3; kx = r9 - ky*3; }
        else          { ci = kg; ky = 0; kx = 0; }
        size_t base = ((size_t)(b*CIN + ci)*PR + (y + ky))*PC + kx + pxb;
        int ro = kb*136 + pxb;
        if constexpr (INTY == 0) {
            const float* src = (const float*)Xin + base;
#pragma unroll
            for (int i2 = 0; i2 < 16; i2++)
                *(unsigned short*)(smc + S_BH + (ro + 8*i2)*2) =
                    __half_as_ushort(__float2half(src[8*i2]));
        } else {
            const unsigned short* src = (const unsigned short*)Xin + base;
#pragma unroll
            for (int i2 = 0; i2 < 16; i2++)
                *(unsigned short*)(smc + S_BH + (ro + 8*i2)*2) = src[8*i2];
        }
        CP_WAIT0();
        __syncthreads();
    }

    const int quad = lane >> 3, qi = lane & 7;

    for (int it = 0; it < KCn; it++) {
        const int s = it & 1;
        const uint32_t stage  = sb + s*S_SZ;
        const uint32_t nstoff = (s^1)*S_SZ;
        const bool hasNext = (it + 1) < KCn;

        float gf[16];
        unsigned short gs[16];
        if (hasNext) {
            const char* sh = (const char*)(Whi + ((size_t)(it+1)*COUT + co0)*40);
            for (int t2 = tid; t2 < 640; t2 += 256) cp16(sb + nstoff + t2*16, sh + t2*16);
            if (ALO) {
                const char* sl = (const char*)(Wlo + ((size_t)(it+1)*COUT + co0)*40);
                for (int t2 = tid; t2 < 640; t2 += 256) cp16(sb + nstoff + S_AL + t2*16, sl + t2*16);
            }
            CP_COMMIT();
            int kg = (it+1)*32 + kb;
            int ci, ky, kx;
            if (KSZ == 3) { ci = kg/9; int r9 = kg - ci*9; ky = r9/3; kx = r9 - ky*3; }
            else          { ci = kg; ky = 0; kx = 0; }
            size_t base = ((size_t)(b*CIN + ci)*PR + (y + ky))*PC + kx + pxb;
            if constexpr (INTY == 0) {
                const float* src = (const float*)Xin + base;
#pragma unroll
                for (int i2 = 0; i2 < 16; i2++) gf[i2] = src[8*i2];
            } else {
                const unsigned short* src = (const unsigned short*)Xin + base;
#pragma unroll
                for (int i2 = 0; i2 < 16; i2++) gs[i2] = src[8*i2];
            }
        }

#pragma unroll
        for (int ks = 0; ks < 2; ks++) {
            const int k0 = ks*16;
            uint32_t Ah[4][4], Al[4][4], Bh[4][2];
            const int arow = warp_m*64 + (quad&1)*8 + qi;
            const int acol = k0 + (quad>>1)*8;
#pragma unroll
            for (int mf = 0; mf < 4; mf++) {
                uint32_t ad = stage + (uint32_t)((arow + mf*16)*40 + acol)*2;
                ldm_x4(Ah[mf], ad);
                if (ALO) ldm_x4(Al[mf], ad + S_AL);
            }
            const int brow = k0 + (quad&1)*8 + qi;
#pragma unroll
            for (int p2 = 0; p2 < 2; p2++) {
                const int n0 = warp_n*32 + p2*16 + (quad>>1)*8;
                uint32_t bd = stage + S_BH + (uint32_t)(brow*136 + n0)*2;
                uint32_t r4[4];
                ldm_x4_t(r4, bd);
                Bh[p2*2][0]=r4[0]; Bh[p2*2][1]=r4[1]; Bh[p2*2+1][0]=r4[2]; Bh[p2*2+1][1]=r4[3];
            }
#pragma unroll
            for (int mf = 0; mf < 4; mf++)
#pragma unroll
                for (int nf = 0; nf < 4; nf++) {
                    mma16816f(acc[mf][nf], Ah[mf], Bh[nf]);
                    if (ALO) mma16816f(acc[mf][nf], Al[mf], Bh[nf]);
                }
        }

        if (hasNext) {
            int ro = kb*136 + pxb;
            if constexpr (INTY == 0) {
#pragma unroll
                for (int i2 = 0; i2 < 16; i2++)
                    *(unsigned short*)(smc + nstoff + S_BH + (ro + 8*i2)*2) =
                        __half_as_ushort(__float2half(gf[i2]));
            } else {
#pragma unroll
                for (int i2 = 0; i2 < 16; i2++)
                    *(unsigned short*)(smc + nstoff + S_BH + (ro + 8*i2)*2) = gs[i2];
            }
        }
        CP_WAIT0();
        __syncthreads();
    }

    const int r = lane >> 2, cpx = (lane & 3)*2;
#pragma unroll
    for (int mf = 0; mf < 4; mf++) {
        int coA = co0 + warp_m*64 + mf*16 + r;
        float b0 = bias[coA], b1 = bias[coA + 8];
#pragma unroll
        for (int nf = 0; nf < 4; nf++) {
            int px = warp_n*32 + nf*8 + cpx;
            float v00 = acc[mf][nf][0] + b0, v01 = acc[mf][nf][1] + b0;
            float v10 = acc[mf][nf][2] + b1, v11 = acc[mf][nf][3] + b1;
            if constexpr (OUTMODE == 1) {
                size_t r0 = ((size_t)(b*COUT + coA    )*PXR + (y+1))*PXC + (px+1);
                size_t r1 = ((size_t)(b*COUT + coA + 8)*PXR + (y+1))*PXC + (px+1);
                Yh[r0]   = __half_as_ushort(__float2half(v00));
                Yh[r0+1] = __half_as_ushort(__float2half(v01));
                Yh[r1]   = __half_as_ushort(__float2half(v10));
                Yh[r1+1] = __half_as_ushort(__float2half(v11));
            } else if constexpr (OUTMODE == 2) {
                uint32_t p0 = (uint32_t)__half_as_ushort(__float2half(v00)) |
                              ((uint32_t)__half_as_ushort(__float2half(v01)) << 16);
                uint32_t p1 = (uint32_t)__half_as_ushort(__float2half(v10)) |
                              ((uint32_t)__half_as_ushort(__float2half(v11)) << 16);
                *(uint32_t*)&Yh[((size_t)(b*COUT + coA    ))*SP + y*WW + px] = p0;
                *(uint32_t*)&Yh[((size_t)(b*COUT + coA + 8))*SP + y*WW + px] = p1;
            } else {
                float2 w0 = {v00, v01}, w1 = {v10, v11};
                *(float2*)&Yf[((size_t)(b*COUT + coA    ))*SP + y*WW + px] = w0;
                *(float2*)&Yf[((size_t)(b*COUT + coA + 8))*SP + y*WW + px] = w1;
            }
        }
    }
}

// ---------------------------------------------------------------------------
// QK Gram matrix + fused row norms (round-14 version; neutral vs separate)
__global__ __launch_bounds__(256)
void qk_mma_kernel(const unsigned short* __restrict__ y2h, float* __restrict__ Sm,
                   float* __restrict__ nq2, float* __restrict__ nk2)
{
    __shared__ __half qs[32][136];
    __shared__ __half ksT[128][40];
    __shared__ float  Ssm[32][32];
    __shared__ float  qrow[32], krow[32];

    const int bh = blockIdx.x;
    const int b  = bh >> 2, h = bh & 3;
    const int s0 = blockIdx.y * 1024;
    const int tid = threadIdx.x, lane = tid & 31, w = tid >> 5;
    const int quad = lane >> 3, qi = lane & 7;

    const unsigned short* q = y2h + (size_t)b*C3*SP + (size_t)(h*CH)*SP;
    const unsigned short* k = q + (size_t)DIM*SP;

    for (int l = tid; l < 1024; l += 256) Ssm[l >> 5][l & 31] = 0.f;
    if (tid < 32) { qrow[tid] = 0.f; krow[tid] = 0.f; }

    const uint32_t sq = smem_to_u32(&qs[0][0]);
    const uint32_t sk = smem_to_u32(&ksT[0][0]);

    float acc[2][4][4];
#pragma unroll
    for (int mf = 0; mf < 2; mf++)
#pragma unroll
        for (int nf = 0; nf < 4; nf++)
#pragma unroll
            for (int e = 0; e < 4; e++) acc[mf][nf][e] = 0.f;

    const int qrow0 = tid >> 4;
    const int qcg0  = tid & 15;
    float sq0 = 0.f, sq1 = 0.f, ksum = 0.f;
    const int kd    = tid >> 3;
    const int ksb   = (tid & 7)*16;

    for (int rnd = 0; rnd < 8; rnd++) {
        const int ss = s0 + rnd*128;
        {
            uint4 v0 = *(const uint4*)&q[(size_t)qrow0*SP + ss + qcg0*8];
            uint4 v1 = *(const uint4*)&q[(size_t)(qrow0+16)*SP + ss + qcg0*8];
            *(uint4*)&qs[qrow0][qcg0*8]    = v0;
            *(uint4*)&qs[qrow0+16][qcg0*8] = v1;
            const __half2* h0 = (const __half2*)&v0;
            const __half2* h1 = (const __half2*)&v1;
#pragma unroll
            for (int e = 0; e < 4; e++) {
                float a0 = __low2float(h0[e]), b0 = __high2float(h0[e]);
                float a1 = __low2float(h1[e]), b1 = __high2float(h1[e]);
                sq0 += a0*a0 + b0*b0;
                sq1 += a1*a1 + b1*b1;
            }
        }
        {
            const unsigned short* kp = &k[(size_t)kd*SP + ss + ksb];
            unsigned short tmp[16];
#pragma unroll
            for (int i2 = 0; i2 < 16; i2++) tmp[i2] = kp[i2];
#pragma unroll
            for (int i2 = 0; i2 < 16; i2++) {
                __half hv = __ushort_as_half(tmp[i2]);
                ksT[ksb + i2][kd] = hv;
                float f = __half2float(hv);
                ksum += f*f;
            }
        }
        __syncthreads();

        uint32_t Af[2][4], Bf[4][2];
#pragma unroll
        for (int mf = 0; mf < 2; mf++) {
            uint32_t ad = sq + (uint32_t)((mf*16 + (quad&1)*8 + qi)*136 + w*16 + (quad>>1)*8)*2;
            ldm_x4(Af[mf], ad);
        }
#pragma unroll
        for (int p2 = 0; p2 < 2; p2++) {
            uint32_t bd = sk + (uint32_t)((w*16 + (quad&1)*8 + qi)*40 + p2*16 + (quad>>1)*8)*2;
            uint32_t r4[4];
            ldm_x4_t(r4, bd);
            Bf[p2*2][0]=r4[0]; Bf[p2*2][1]=r4[1]; Bf[p2*2+1][0]=r4[2]; Bf[p2*2+1][1]=r4[3];
        }
#pragma unroll
        for (int mf = 0; mf < 2; mf++)
#pragma unroll
            for (int nf = 0; nf < 4; nf++)
                mma16816f(acc[mf][nf], Af[mf], Bf[nf]);
        __syncthreads();
    }

    atomicAdd(&qrow[qrow0], sq0);
    atomicAdd(&qrow[qrow0+16], sq1);
    atomicAdd(&krow[kd], ksum);

    const int r = lane >> 2, cpx = (lane & 3)*2;
#pragma unroll
    for (int mf = 0; mf < 2; mf++)
#pragma unroll
        for (int nf = 0; nf < 4; nf++) {
            atomicAdd(&Ssm[mf*16 + r    ][nf*8 + cpx    ], acc[mf][nf][0]);
            atomicAdd(&Ssm[mf*16 + r    ][nf*8 + cpx + 1], acc[mf][nf][1]);
            atomicAdd(&Ssm[mf*16 + r + 8][nf*8 + cpx    ], acc[mf][nf][2]);
            atomicAdd(&Ssm[mf*16 + r + 8][nf*8 + cpx + 1], acc[mf][nf][3]);
        }
    __syncthreads();
    for (int l = tid; l < 1024; l += 256)
        atomicAdd(&Sm[bh*1024 + l], Ssm[l >> 5][l & 31]);
    if (tid < 32) {
        atomicAdd(&nq2[b*DIM + h*CH + tid], qrow[tid]);
        atomicAdd(&nk2[b*DIM + h*CH + tid], krow[tid]);
    }
}

__global__ __launch_bounds__(1024)
void softmax_kernel(const float* __restrict__ Sm, const float* __restrict__ nq2,
                    const float* __restrict__ nk2, const float* __restrict__ temp,
                    float* __restrict__ Am)
{
    const int bh = blockIdx.x;
    const int b  = bh >> 2, h = bh & 3;
    const int c  = threadIdx.x >> 5;
    const int d  = threadIdx.x & 31;

    float qn = fmaxf(sqrtf(nq2[b*DIM + h*CH + c]), 1e-12f);
    float kn = fmaxf(sqrtf(nk2[b*DIM + h*CH + d]), 1e-12f);
    float v  = Sm[bh*1024 + c*32 + d] / (qn * kn) * temp[h];

    float m = v;
#pragma unroll
    for (int o = 16; o; o >>= 1) m = fmaxf(m, __shfl_xor_sync(~0u, m, o));
    float e = __expf(v - m);
    float s = e;
#pragma unroll
    for (int o = 16; o; o >>= 1) s += __shfl_xor_sync(~0u, s, o);
    Am[bh*1024 + c*32 + d] = e / s;
}

// ---------------------------------------------------------------------------
// AV on mma.sync
__global__ __launch_bounds__(256)
void av_mma_kernel(const unsigned short* __restrict__ y2h, const float* __restrict__ Am,
                   unsigned short* __restrict__ aoh)
{
    __shared__ __half As[32][40];
    __shared__ __half Vs[32][136];

    const int bh = blockIdx.x;
    const int b  = bh >> 2, h = bh & 3;
    const int s0 = blockIdx.y * 1024;
    const int tid = threadIdx.x, lane = tid & 31, w = tid >> 5;
    const int quad = lane >> 3, qi = lane & 7;

    const unsigned short* v = y2h + (size_t)b*C3*SP + (size_t)(2*DIM + h*CH)*SP;
    unsigned short* o = aoh + (size_t)b*DIM*SP + (size_t)(h*CH)*SP;

    for (int l = tid; l < 1024; l += 256)
        As[l >> 5][l & 31] = __float2half(Am[bh*1024 + l]);

    const uint32_t sa = smem_to_u32(&As[0][0]);
    const uint32_t sv = smem_to_u32(&Vs[0][0]);
    const int r = lane >> 2, cpx = (lane & 3)*2;

    for (int rnd = 0; rnd < 8; rnd++) {
        const int ss = s0 + rnd*128;
        for (int t2 = tid; t2 < 512; t2 += 256) {
            int row = t2 >> 4, cg = t2 & 15;
            *(uint4*)&Vs[row][cg*8] = *(const uint4*)&v[(size_t)row*SP + ss + cg*8];
        }
        __syncthreads();

        float acc[2][2][4];
#pragma unroll
        for (int mf = 0; mf < 2; mf++)
#pragma unroll
            for (int nf = 0; nf < 2; nf++)
#pragma unroll
                for (int e = 0; e < 4; e++) acc[mf][nf][e] = 0.f;

#pragma unroll
        for (int ks = 0; ks < 2; ks++) {
            const int k0 = ks*16;
            uint32_t Af[2][4], Bf[2][2];
#pragma unroll
            for (int mf = 0; mf < 2; mf++) {
                uint32_t ad = sa + (uint32_t)((mf*16 + (quad&1)*8 + qi)*40 + k0 + (quad>>1)*8)*2;
                ldm_x4(Af[mf], ad);
            }
            {
                uint32_t bd = sv + (uint32_t)((k0 + (quad&1)*8 + qi)*136 + w*16 + (quad>>1)*8)*2;
                uint32_t r4[4];
                ldm_x4_t(r4, bd);
                Bf[0][0]=r4[0]; Bf[0][1]=r4[1]; Bf[1][0]=r4[2]; Bf[1][1]=r4[3];
            }
#pragma unroll
            for (int mf = 0; mf < 2; mf++)
#pragma unroll
                for (int nf = 0; nf < 2; nf++)
                    mma16816f(acc[mf][nf], Af[mf], Bf[nf]);
        }

#pragma unroll
        for (int mf = 0; mf < 2; mf++)
#pragma unroll
            for (int nf = 0; nf < 2; nf++) {
                int c0 = mf*16 + r;
                int sx = ss + w*16 + nf*8 + cpx;
                uint32_t p0 = (uint32_t)__half_as_ushort(__float2half(acc[mf][nf][0])) |
                              ((uint32_t)__half_as_ushort(__float2half(acc[mf][nf][1])) << 16);
                uint32_t p1 = (uint32_t)__half_as_ushort(__float2half(acc[mf][nf][2])) |
                              ((uint32_t)__half_as_ushort(__float2half(acc[mf][nf][3])) << 16);
                *(uint32_t*)&o[(size_t)(c0    )*SP + sx] = p0;
                *(uint32_t*)&o[(size_t)(c0 + 8)*SP + sx] = p1;
            }
        __syncthreads();
    }
}

// ---------------------------------------------------------------------------
extern "C" void kernel_launch(void* const* d_in, const int* in_sizes, int n_in,
                              void* d_out, int out_size)
{
    const float* x      = (const float*)d_in[0];
    const float* qkv_r  = (const float*)d_in[1];
    const float* qkv_i  = (const float*)d_in[2];
    const float* qkv_j  = (const float*)d_in[3];
    const float* qkv_k  = (const float*)d_in[4];
    const float* qkv_b  = (const float*)d_in[5];
    const float* dw_r   = (const float*)d_in[6];
    const float* dw_i   = (const float*)d_in[7];
    const float* dw_j   = (const float*)d_in[8];
    const float* dw_k   = (const float*)d_in[9];
    const float* dw_b   = (const float*)d_in[10];
    const float* po_r   = (const float*)d_in[11];
    const float* po_i   = (const float*)d_in[12];
    const float* po_j   = (const float*)d_in[13];
    const float* po_k   = (const float*)d_in[14];
    const float* po_b   = (const float*)d_in[15];
    const float* temper = (const float*)d_in[16];
    float* out = (float*)d_out;

    __half *Wq_hi, *Wq_lo, *Wd_hi, *Wp_hi, *Wp_lo;
    unsigned short *Xpd, *y2h, *aoh;
    float *nq2, *nk2, *Sm, *Am;
    cudaGetSymbolAddress((void**)&Wq_hi, g_Wq_hi);
    cudaGetSymbolAddress((void**)&Wq_lo, g_Wq_lo);
    cudaGetSymbolAddress((void**)&Wd_hi, g_Wd_hi);
    cudaGetSymbolAddress((void**)&Wp_hi, g_Wp_hi);
    cudaGetSymbolAddress((void**)&Wp_lo, g_Wp_lo);
    cudaGetSymbolAddress((void**)&Xpd, g_Xpd);
    cudaGetSymbolAddress((void**)&y2h, g_y2h);
    cudaGetSymbolAddress((void**)&aoh, g_aoh);
    cudaGetSymbolAddress((void**)&nq2, g_nq2);
    cudaGetSymbolAddress((void**)&nk2, g_nk2);
    cudaGetSymbolAddress((void**)&Sm, g_S);
    cudaGetSymbolAddress((void**)&Am, g_A);

    const int SMQ = 58368;   // 2-pass A-split stages
    const int SM1 = 37888;   // 1-pass stages
    cudaFuncSetAttribute(convmma_kernel<128,1,384,true,0,1>,
                         cudaFuncAttributeMaxDynamicSharedMemorySize, SMQ);
    cudaFuncSetAttribute(convmma_kernel<384,3,384,false,1,2>,
                         cudaFuncAttributeMaxDynamicSharedMemorySize, SM1);
    cudaFuncSetAttribute(convmma_kernel<128,1,128,true,1,0>,
                         cudaFuncAttributeMaxDynamicSharedMemorySize, SMQ);

    // 1) fused prep
    prep_kernel<<<(NTOT + 255)/256, 256>>>(
        qkv_r, qkv_i, qkv_j, qkv_k, dw_r, dw_i, dw_j, dw_k, po_r, po_i, po_j, po_k,
        Wq_hi, Wq_lo, Wd_hi, Wp_hi, Wp_lo, Xpd, Sm, nq2, nk2);

    // 2) qkv 1x1 conv
    convmma_kernel<128,1,384,true,0,1><<<dim3(BATCH*HH, 3), 256, SMQ>>>(
        Wq_hi, Wq_lo, x, qkv_b, nullptr, Xpd, HH, WW);

    // 3) dw 3x3 conv (round-13 direct-gather pipeline)
    convmma_kernel<384,3,384,false,1,2><<<dim3(BATCH*HH, 3), 256, SM1>>>(
        Wd_hi, Wd_hi, Xpd, dw_b, nullptr, y2h, PXR, PXC);

    // 4) attention (norms fused into qk)
    qk_mma_kernel<<<dim3(8, 16), 256>>>(y2h, Sm, nq2, nk2);
    softmax_kernel<<<8, 1024>>>(Sm, nq2, nk2, temper, Am);
    av_mma_kernel<<<dim3(8, 16), 256>>>(y2h, Am, aoh);

    // 5) po 1x1 conv -> out
    convmma_kernel<128,1,128,true,1,0><<<dim3(BATCH*HH, 1), 256, SMQ>>>(
        Wp_hi, Wp_lo, aoh, po_b, out, nullptr, HH, WW);
}